// round 16
// baseline (speedup 1.0000x reference)
#include <cuda_runtime.h>
#include <math.h>
#include <stdint.h>

// Problem constants
constexpr int S_LEN = 4096;
constexpr int BATCH = 2;
constexpr int EMB   = 512;   // E and also H*D
constexpr int NH    = 8;
constexpr int DH    = 64;
constexpr int HALF  = 256;   // sliding window half-width
constexpr int ROWS  = BATCH * S_LEN;  // 8192
constexpr int KPR   = EMB / 2;        // 256 kpairs per row
constexpr int SHALF = S_LEN / 2;      // 2048 token-pairs

// Scratch (allocation-free rule: __device__ globals)
__device__ uint32_t g_qh[(size_t)ROWS * KPR];
__device__ uint32_t g_ql[(size_t)ROWS * KPR];
__device__ uint32_t g_kh[(size_t)ROWS * KPR];
__device__ uint32_t g_kl[(size_t)ROWS * KPR];
// V transposed planes: [b][dim g][token-pair tp] u32 (bf16x2: t low, t+1 high)
__device__ uint32_t g_vth[(size_t)BATCH * EMB * SHALF];
__device__ uint32_t g_vtl[(size_t)BATCH * EMB * SHALF];
__device__ float    g_att[(size_t)ROWS * EMB];

// ---------------------------------------------------------------------------
// helpers
// ---------------------------------------------------------------------------
__device__ __forceinline__ void split2(float x0, float x1,
                                       uint32_t& hp, uint32_t& lp) {
    asm("cvt.rn.bf16x2.f32 %0, %1, %2;" : "=r"(hp) : "f"(x1), "f"(x0));
    float h0 = __uint_as_float(hp << 16);
    float h1 = __uint_as_float(hp & 0xffff0000u);
    float r0 = x0 - h0;
    float r1 = x1 - h1;
    asm("cvt.rn.bf16x2.f32 %0, %1, %2;" : "=r"(lp) : "f"(r1), "f"(r0));
}

__device__ __forceinline__ void mma_bf16(float d[4], const uint32_t a[4],
                                         const uint32_t b[2]) {
    asm volatile(
        "mma.sync.aligned.m16n8k16.row.col.f32.bf16.bf16.f32 "
        "{%0,%1,%2,%3}, {%4,%5,%6,%7}, {%8,%9}, {%0,%1,%2,%3};\n"
        : "+f"(d[0]), "+f"(d[1]), "+f"(d[2]), "+f"(d[3])
        : "r"(a[0]), "r"(a[1]), "r"(a[2]), "r"(a[3]), "r"(b[0]), "r"(b[1]));
}

__device__ __forceinline__ void ldsm_x4(uint32_t r[4], uint32_t addr) {
    asm volatile(
        "ldmatrix.sync.aligned.m8n8.x4.shared.b16 {%0,%1,%2,%3}, [%4];"
        : "=r"(r[0]), "=r"(r[1]), "=r"(r[2]), "=r"(r[3]) : "r"(addr));
}

__device__ __forceinline__ uint32_t smem_u32(const void* p) {
    return (uint32_t)__cvta_generic_to_shared(p);
}

// ---------------------------------------------------------------------------
// Split-bf16 tensor-core GEMM, single-buffered smem, 2 CTAs/SM (R13 form).
// C[M,N] = A[M,K] @ B[K,N]. MODE 0: fp32 C. MODE 1: bf16x2 hi/lo planes
// [row][kpair]. MODE 2: TRANSPOSED hi/lo planes [b][dim][token-pair] (for V).
// ---------------------------------------------------------------------------
constexpr int GBM = 128, GBN = 128, GBK = 32;
constexpr int KP  = GBK / 2;
constexpr int ASTR = 20;
constexpr int BSTR = 136;
constexpr int A_STAGE = GBM * ASTR;     // 2560
constexpr int B_STAGE = KP * BSTR;      // 2176
constexpr int GEMM_SMEM_BYTES = 2 * (A_STAGE + B_STAGE) * 4;  // 37888

template <int MODE>
__global__ __launch_bounds__(256, 2) void gemm_bf16_kernel(
    const float* __restrict__ A, const float* __restrict__ B,
    float* __restrict__ C, uint32_t* __restrict__ Ch, uint32_t* __restrict__ Cl,
    int M, int N, int K)
{
    extern __shared__ uint32_t sm[];
    uint32_t* sAh = sm;
    uint32_t* sAl = sAh + A_STAGE;
    uint32_t* sBh = sAl + A_STAGE;
    uint32_t* sBl = sBh + B_STAGE;

    const int tid  = threadIdx.x;
    const int lane = tid & 31;
    const int wid  = tid >> 5;
    const int m_base = (wid >> 2) * 64;
    const int n_base = (wid & 3) * 32;
    const int row0 = blockIdx.y * GBM;
    const int col0 = blockIdx.x * GBN;

    const int arow  = tid >> 2;
    const int acolg = (tid & 3) * 8;
    const int akp   = (tid & 3) * 4;
    const int brow = tid >> 5;
    const int bcol = (tid & 31) * 4;

    const float* pA0 = A + (size_t)(row0 + arow) * K + acolg;
    const float* pA1 = A + (size_t)(row0 + arow + 64) * K + acolg;
    const float* pB00 = B + (size_t)(2 * brow) * N + col0 + bcol;
    const float* pB01 = B + (size_t)(2 * brow + 1) * N + col0 + bcol;
    const float* pB10 = B + (size_t)(2 * (brow + 8)) * N + col0 + bcol;
    const float* pB11 = B + (size_t)(2 * (brow + 8) + 1) * N + col0 + bcol;

    const int NT = K / GBK;   // 16
    const int gr = lane >> 2;
    const int qc = lane & 3;

    float acc[4][4][4] = {};

    for (int kt = 0; kt < NT; kt++) {
        const int ko = kt * GBK;
        float4 fa00 = *(const float4*)(pA0 + ko);
        float4 fa01 = *(const float4*)(pA0 + ko + 4);
        float4 fa10 = *(const float4*)(pA1 + ko);
        float4 fa11 = *(const float4*)(pA1 + ko + 4);
        float4 fb00 = *(const float4*)(pB00 + (size_t)ko * N);
        float4 fb01 = *(const float4*)(pB01 + (size_t)ko * N);
        float4 fb10 = *(const float4*)(pB10 + (size_t)ko * N);
        float4 fb11 = *(const float4*)(pB11 + (size_t)ko * N);

        if (kt > 0) __syncthreads();

        {
            uint32_t h0, l0, h1, l1, h2, l2, h3, l3;
            split2(fa00.x, fa00.y, h0, l0);
            split2(fa00.z, fa00.w, h1, l1);
            split2(fa01.x, fa01.y, h2, l2);
            split2(fa01.z, fa01.w, h3, l3);
            *(uint4*)&sAh[arow * ASTR + akp] = make_uint4(h0, h1, h2, h3);
            *(uint4*)&sAl[arow * ASTR + akp] = make_uint4(l0, l1, l2, l3);
            split2(fa10.x, fa10.y, h0, l0);
            split2(fa10.z, fa10.w, h1, l1);
            split2(fa11.x, fa11.y, h2, l2);
            split2(fa11.z, fa11.w, h3, l3);
            *(uint4*)&sAh[(arow + 64) * ASTR + akp] = make_uint4(h0, h1, h2, h3);
            *(uint4*)&sAl[(arow + 64) * ASTR + akp] = make_uint4(l0, l1, l2, l3);
            split2(fb00.x, fb01.x, h0, l0);
            split2(fb00.y, fb01.y, h1, l1);
            split2(fb00.z, fb01.z, h2, l2);
            split2(fb00.w, fb01.w, h3, l3);
            *(uint4*)&sBh[brow * BSTR + bcol] = make_uint4(h0, h1, h2, h3);
            *(uint4*)&sBl[brow * BSTR + bcol] = make_uint4(l0, l1, l2, l3);
            split2(fb10.x, fb11.x, h0, l0);
            split2(fb10.y, fb11.y, h1, l1);
            split2(fb10.z, fb11.z, h2, l2);
            split2(fb10.w, fb11.w, h3, l3);
            *(uint4*)&sBh[(brow + 8) * BSTR + bcol] = make_uint4(h0, h1, h2, h3);
            *(uint4*)&sBl[(brow + 8) * BSTR + bcol] = make_uint4(l0, l1, l2, l3);
        }
        __syncthreads();

        #pragma unroll
        for (int ks = 0; ks < 2; ks++) {
            const int kp0 = ks * 8 + qc;
            uint32_t ah[4][4], al[4][4], bh[4][2], bl[4][2];
            #pragma unroll
            for (int mt = 0; mt < 4; mt++) {
                const int m = m_base + mt * 16 + gr;
                ah[mt][0] = sAh[m * ASTR + kp0];
                ah[mt][1] = sAh[(m + 8) * ASTR + kp0];
                ah[mt][2] = sAh[m * ASTR + kp0 + 4];
                ah[mt][3] = sAh[(m + 8) * ASTR + kp0 + 4];
                al[mt][0] = sAl[m * ASTR + kp0];
                al[mt][1] = sAl[(m + 8) * ASTR + kp0];
                al[mt][2] = sAl[m * ASTR + kp0 + 4];
                al[mt][3] = sAl[(m + 8) * ASTR + kp0 + 4];
            }
            #pragma unroll
            for (int nt = 0; nt < 4; nt++) {
                const int n = n_base + nt * 8 + gr;
                bh[nt][0] = sBh[kp0 * BSTR + n];
                bh[nt][1] = sBh[(kp0 + 4) * BSTR + n];
                bl[nt][0] = sBl[kp0 * BSTR + n];
                bl[nt][1] = sBl[(kp0 + 4) * BSTR + n];
            }
            #pragma unroll
            for (int mt = 0; mt < 4; mt++)
                #pragma unroll
                for (int nt = 0; nt < 4; nt++) {
                    mma_bf16(acc[mt][nt], ah[mt], bh[nt]);
                    mma_bf16(acc[mt][nt], ah[mt], bl[nt]);
                    mma_bf16(acc[mt][nt], al[mt], bh[nt]);
                }
        }
    }

    #pragma unroll
    for (int mt = 0; mt < 4; mt++) {
        #pragma unroll
        for (int nt = 0; nt < 4; nt++) {
            if constexpr (MODE == 2) {
                // transposed split output: pack token pairs via shfl_xor(4)
                float e0 = acc[mt][nt][0], e1 = acc[mt][nt][1];
                float e2 = acc[mt][nt][2], e3 = acc[mt][nt][3];
                float p0 = __shfl_xor_sync(0xffffffffu, e0, 4);
                float p1 = __shfl_xor_sync(0xffffffffu, e1, 4);
                float p2 = __shfl_xor_sync(0xffffffffu, e2, 4);
                float p3 = __shfl_xor_sync(0xffffffffu, e3, 4);
                if ((gr & 1) == 0) {
                    int r = row0 + m_base + mt * 16 + gr;   // even token
                    int bb = r >> 12;
                    int t  = r & (S_LEN - 1);
                    int c  = col0 + n_base + nt * 8 + 2 * qc;
                    size_t b0 = ((size_t)bb * EMB + c) * SHALF + (t >> 1);
                    uint32_t hp, lp;
                    split2(e0, p0, hp, lp);
                    Ch[b0] = hp;               Cl[b0] = lp;
                    split2(e1, p1, hp, lp);
                    Ch[b0 + SHALF] = hp;       Cl[b0 + SHALF] = lp;
                    split2(e2, p2, hp, lp);
                    Ch[b0 + 4] = hp;           Cl[b0 + 4] = lp;
                    split2(e3, p3, hp, lp);
                    Ch[b0 + SHALF + 4] = hp;   Cl[b0 + SHALF + 4] = lp;
                }
            } else {
                int r = row0 + m_base + mt * 16 + gr;
                int c = col0 + n_base + nt * 8 + 2 * qc;
                if constexpr (MODE == 1) {
                    int kp = c >> 1;
                    uint32_t hp, lp;
                    split2(acc[mt][nt][0], acc[mt][nt][1], hp, lp);
                    Ch[(size_t)r * KPR + kp] = hp;
                    Cl[(size_t)r * KPR + kp] = lp;
                    split2(acc[mt][nt][2], acc[mt][nt][3], hp, lp);
                    Ch[(size_t)(r + 8) * KPR + kp] = hp;
                    Cl[(size_t)(r + 8) * KPR + kp] = lp;
                } else {
                    *(float2*)&C[(size_t)r * N + c] =
                        make_float2(acc[mt][nt][0], acc[mt][nt][1]);
                    *(float2*)&C[(size_t)(r + 8) * N + c] =
                        make_float2(acc[mt][nt][2], acc[mt][nt][3]);
                }
            }
        }
    }
}

// ---------------------------------------------------------------------------
// Attention (R12-validated core): split-bf16, ldmatrix, pre-split inputs,
// fixed-max softmax, register-resident P. V now arrives PRE-TRANSPOSED
// (pure uint4 copy, no PRMT repack). 256 threads, 6 chunks of 96, 2 CTAs/SM.
// ---------------------------------------------------------------------------
constexpr int AQT = 64;
constexpr int AKT = 96;
constexpr int NCHUNK = 6;
constexpr int QSTR2 = 36;
constexpr int KSTR2 = 36;
constexpr int VSTR2 = 52;
constexpr int ATHREADS = 256;
constexpr float FIXM = 12.0f;

constexpr int OFF_QH = 0;
constexpr int OFF_QL = OFF_QH + AQT * QSTR2;
constexpr int OFF_KH = OFF_QL + AQT * QSTR2;
constexpr int OFF_KL = OFF_KH + AKT * KSTR2;
constexpr int OFF_VH = OFF_KL + AKT * KSTR2;
constexpr int OFF_VL = OFF_VH + 64 * VSTR2;
constexpr int OFF_RED = OFF_VL + 64 * VSTR2;
constexpr int OFF_ORED = OFF_RED + 128;
constexpr int ATTN_SMEM_WORDS = OFF_ORED + 64 * 66;
constexpr int ATTN_SMEM_BYTES = ATTN_SMEM_WORDS * 4;  // 90112

__global__ __launch_bounds__(ATHREADS, 2) void attn_tc_kernel()
{
    extern __shared__ uint32_t sm[];
    uint32_t* sQh = sm + OFF_QH;
    uint32_t* sQl = sm + OFF_QL;
    uint32_t* sKh = sm + OFF_KH;
    uint32_t* sKl = sm + OFF_KL;
    uint32_t* sVh = sm + OFF_VH;
    uint32_t* sVl = sm + OFF_VL;
    float* red  = (float*)(sm + OFF_RED);
    float* ored = (float*)(sm + OFF_ORED);

    const int tid  = threadIdx.x;
    const int lane = tid & 31;
    const int wid  = tid >> 5;
    const int gr = lane >> 2;
    const int qc = lane & 3;
    const int wm = wid >> 1;
    const int wn = wid & 1;
    const int m0 = wm * 16;

    const int t0 = blockIdx.x * AQT;
    const int h  = blockIdx.y;
    const int b  = blockIdx.z;
    const float slope = exp2f(-(float)(h + 1));

    const uint32_t* Qh_p = g_qh + ((size_t)(b * S_LEN + t0)) * KPR + h * 32;
    const uint32_t* Ql_p = g_ql + ((size_t)(b * S_LEN + t0)) * KPR + h * 32;
    const uint32_t* Kh_p = g_kh + ((size_t)b * S_LEN) * KPR + h * 32;
    const uint32_t* Kl_p = g_kl + ((size_t)b * S_LEN) * KPR + h * 32;
    const uint32_t* Vth_p = g_vth + ((size_t)b * EMB + h * DH) * SHALF;
    const uint32_t* Vtl_p = g_vtl + ((size_t)b * EMB + h * DH) * SHALF;
    float* Ob = g_att + (size_t)b * S_LEN * EMB + h * DH;

    const int lrow8  = (lane & 7);
    const int lmsel  = (lane >> 3) & 1;
    const int lhsel  = (lane >> 4) & 1;

    const uint32_t qh_base = smem_u32(sQh) +
        (((m0 + lrow8 + lmsel * 8) * QSTR2) + lhsel * 4) * 4;
    const uint32_t ql_base = qh_base + (OFF_QL - OFF_QH) * 4;
    const int nbase = wn * 48;
    const uint32_t kh_base = smem_u32(sKh) +
        (((nbase + lrow8 + lhsel * 8) * KSTR2) + lmsel * 4) * 4;
    const uint32_t kl_base = kh_base + (OFF_KL - OFF_KH) * 4;
    const uint32_t vh_base = smem_u32(sVh) +
        (((lrow8 + lhsel * 8) * VSTR2) + wn * 24 + lmsel * 4) * 4;
    const uint32_t vl_base = vh_base + (OFF_VL - OFF_VH) * 4;

    for (int idx = tid; idx < 512; idx += ATHREADS) {
        int q = idx >> 3;
        int j = idx & 7;
        uint4 vh = *(const uint4*)&Qh_p[(size_t)q * KPR + j * 4];
        uint4 vl = *(const uint4*)&Ql_p[(size_t)q * KPR + j * 4];
        *(uint4*)&sQh[q * QSTR2 + j * 4] = vh;
        *(uint4*)&sQl[q * QSTR2 + j * 4] = vl;
    }

    float o[8][4] = {};
    float sum0 = 0.f, sum1 = 0.f;

    const int base = t0 - HALF;

    #pragma unroll 1
    for (int c = 0; c < NCHUNK; c++) {
        const int cs = base + c * AKT;
        if (cs + AKT <= 0 || cs >= S_LEN) continue;

        // ---- K chunk: pure copy ----
        for (int idx = tid; idx < 768; idx += ATHREADS) {
            int key = idx >> 3;
            int j = idx & 7;
            int T = cs + key;
            uint4 vh = make_uint4(0, 0, 0, 0);
            uint4 vl = make_uint4(0, 0, 0, 0);
            if (T >= 0 && T < S_LEN) {
                vh = *(const uint4*)&Kh_p[(size_t)T * KPR + j * 4];
                vl = *(const uint4*)&Kl_p[(size_t)T * KPR + j * 4];
            }
            *(uint4*)&sKh[key * KSTR2 + j * 4] = vh;
            *(uint4*)&sKl[key * KSTR2 + j * 4] = vl;
        }
        // ---- V chunk: pure copy of pre-transposed planes ----
        {
            const int tp0 = cs >> 1;
            for (int idx = tid; idx < 1536; idx += ATHREADS) {
                int plane = idx >= 768;
                int rowj = plane ? idx - 768 : idx;
                int d = rowj / 12;
                int jj = rowj - d * 12;
                int tp = tp0 + jj * 4;
                uint4 v = make_uint4(0, 0, 0, 0);
                const uint32_t* src = plane ? Vtl_p : Vth_p;
                if (tp >= 0 && tp < SHALF)
                    v = *(const uint4*)&src[(size_t)d * SHALF + tp];
                uint32_t* dst = plane ? sVl : sVh;
                *(uint4*)&dst[d * VSTR2 + jj * 4] = v;
            }
        }
        __syncthreads();

        // ---- S = Q @ K^T ----
        float s[6][4];
        #pragma unroll
        for (int nt = 0; nt < 6; nt++)
            #pragma unroll
            for (int i = 0; i < 4; i++) s[nt][i] = 0.f;

        #pragma unroll
        for (int ks = 0; ks < 4; ks++) {
            uint32_t ah[4], al[4];
            ldsm_x4(ah, qh_base + ks * 32);
            ldsm_x4(al, ql_base + ks * 32);
            #pragma unroll
            for (int ntp = 0; ntp < 3; ntp++) {
                uint32_t bh[4], bl[4];
                ldsm_x4(bh, kh_base + ks * 32 + ntp * (16 * KSTR2 * 4));
                ldsm_x4(bl, kl_base + ks * 32 + ntp * (16 * KSTR2 * 4));
                mma_bf16(s[2 * ntp],     ah, bh);
                mma_bf16(s[2 * ntp],     ah, bl);
                mma_bf16(s[2 * ntp],     al, bh);
                mma_bf16(s[2 * ntp + 1], ah, bh + 2);
                mma_bf16(s[2 * ntp + 1], ah, bl + 2);
                mma_bf16(s[2 * ntp + 1], al, bh + 2);
            }
        }

        // ---- fixed-max softmax -> P packed into PV A-fragments ----
        const int trow0 = t0 + m0 + gr;
        const int trow1 = trow0 + 8;
        uint32_t pah[3][4], pal[3][4];
        #pragma unroll
        for (int nt = 0; nt < 6; nt++) {
            int T0 = cs + nbase + nt * 8 + 2 * qc;
            int T1 = T0 + 1;
            bool in0 = (T0 >= 0) && (T0 < S_LEN);
            bool in1 = (T1 >= 0) && (T1 < S_LEN);
            int a00 = abs(trow0 - T0), a01 = abs(trow0 - T1);
            int a10 = abs(trow1 - T0), a11 = abs(trow1 - T1);
            float p00 = (in0 && a00 <= HALF)
                ? __expf(fmaf(s[nt][0], 0.125f, fmaf(-slope, (float)a00, -FIXM))) : 0.f;
            float p01 = (in1 && a01 <= HALF)
                ? __expf(fmaf(s[nt][1], 0.125f, fmaf(-slope, (float)a01, -FIXM))) : 0.f;
            float p10 = (in0 && a10 <= HALF)
                ? __expf(fmaf(s[nt][2], 0.125f, fmaf(-slope, (float)a10, -FIXM))) : 0.f;
            float p11 = (in1 && a11 <= HALF)
                ? __expf(fmaf(s[nt][3], 0.125f, fmaf(-slope, (float)a11, -FIXM))) : 0.f;
            sum0 += p00 + p01;
            sum1 += p10 + p11;
            int ks = nt >> 1;
            int half = (nt & 1) * 2;
            uint32_t hp, lp;
            split2(p00, p01, hp, lp);
            pah[ks][half + 0] = hp;  pal[ks][half + 0] = lp;
            split2(p10, p11, hp, lp);
            pah[ks][half + 1] = hp;  pal[ks][half + 1] = lp;
        }

        // ---- O += P @ V ----
        #pragma unroll
        for (int ks = 0; ks < 3; ks++) {
            #pragma unroll
            for (int dt = 0; dt < 4; dt++) {
                uint32_t bh[4], bl[4];
                uint32_t off = (uint32_t)(dt * 16 * VSTR2 * 4 + ks * 32);
                ldsm_x4(bh, vh_base + off);
                ldsm_x4(bl, vl_base + off);
                mma_bf16(o[2 * dt],     pah[ks], bh);
                mma_bf16(o[2 * dt],     pah[ks], bl);
                mma_bf16(o[2 * dt],     pal[ks], bh);
                mma_bf16(o[2 * dt + 1], pah[ks], bh + 2);
                mma_bf16(o[2 * dt + 1], pah[ks], bl + 2);
                mma_bf16(o[2 * dt + 1], pal[ks], bh + 2);
            }
        }
        __syncthreads();
    }

    sum0 += __shfl_xor_sync(0xffffffffu, sum0, 1);
    sum0 += __shfl_xor_sync(0xffffffffu, sum0, 2);
    sum1 += __shfl_xor_sync(0xffffffffu, sum1, 1);
    sum1 += __shfl_xor_sync(0xffffffffu, sum1, 2);
    if (qc == 0) {
        red[(m0 + gr) * 2 + wn] = sum0;
        red[(m0 + gr + 8) * 2 + wn] = sum1;
    }
    if (wn == 1) {
        #pragma unroll
        for (int nt = 0; nt < 8; nt++) {
            int d = nt * 8 + 2 * qc;
            *(float2*)&ored[(m0 + gr) * 66 + d] = make_float2(o[nt][0], o[nt][1]);
            *(float2*)&ored[(m0 + gr + 8) * 66 + d] = make_float2(o[nt][2], o[nt][3]);
        }
    }
    __syncthreads();

    if (wn == 0) {
        const int trow0 = t0 + m0 + gr;
        const float inv0 = 1.0f / (red[(m0 + gr) * 2] + red[(m0 + gr) * 2 + 1]);
        const float inv1 = 1.0f / (red[(m0 + gr + 8) * 2] + red[(m0 + gr + 8) * 2 + 1]);
        #pragma unroll
        for (int nt = 0; nt < 8; nt++) {
            int d = nt * 8 + 2 * qc;
            float2 p0 = *(float2*)&ored[(m0 + gr) * 66 + d];
            float2 p1 = *(float2*)&ored[(m0 + gr + 8) * 66 + d];
            *(float2*)&Ob[(size_t)trow0 * EMB + d] =
                make_float2((o[nt][0] + p0.x) * inv0, (o[nt][1] + p0.y) * inv0);
            *(float2*)&Ob[(size_t)(trow0 + 8) * EMB + d] =
                make_float2((o[nt][2] + p1.x) * inv1, (o[nt][3] + p1.y) * inv1);
        }
    }
}

// ---------------------------------------------------------------------------
extern "C" void kernel_launch(void* const* d_in, const int* in_sizes, int n_in,
                              void* d_out, int out_size)
{
    (void)in_sizes; (void)n_in; (void)out_size;
    const float* inputs_q  = (const float*)d_in[0];
    const float* inputs_kv = (const float*)d_in[1];
    const float* w_q = (const float*)d_in[2];
    const float* w_k = (const float*)d_in[3];
    const float* w_v = (const float*)d_in[4];
    const float* w_o = (const float*)d_in[5];
    float* out = (float*)d_out;

    uint32_t *qh, *ql, *kh, *kl, *vth, *vtl;
    float* ab;
    cudaGetSymbolAddress((void**)&qh, g_qh);
    cudaGetSymbolAddress((void**)&ql, g_ql);
    cudaGetSymbolAddress((void**)&kh, g_kh);
    cudaGetSymbolAddress((void**)&kl, g_kl);
    cudaGetSymbolAddress((void**)&vth, g_vth);
    cudaGetSymbolAddress((void**)&vtl, g_vtl);
    cudaGetSymbolAddress((void**)&ab, g_att);

    cudaFuncSetAttribute(gemm_bf16_kernel<0>,
                         cudaFuncAttributeMaxDynamicSharedMemorySize,
                         GEMM_SMEM_BYTES);
    cudaFuncSetAttribute(gemm_bf16_kernel<1>,
                         cudaFuncAttributeMaxDynamicSharedMemorySize,
                         GEMM_SMEM_BYTES);
    cudaFuncSetAttribute(gemm_bf16_kernel<2>,
                         cudaFuncAttributeMaxDynamicSharedMemorySize,
                         GEMM_SMEM_BYTES);
    cudaFuncSetAttribute(attn_tc_kernel,
                         cudaFuncAttributeMaxDynamicSharedMemorySize,
                         ATTN_SMEM_BYTES);

    dim3 gGemm(EMB / GBN, ROWS / GBM);   // (4, 64)
    gemm_bf16_kernel<1><<<gGemm, 256, GEMM_SMEM_BYTES>>>(
        inputs_q,  w_q, nullptr, qh, ql, ROWS, EMB, EMB);
    gemm_bf16_kernel<1><<<gGemm, 256, GEMM_SMEM_BYTES>>>(
        inputs_kv, w_k, nullptr, kh, kl, ROWS, EMB, EMB);
    gemm_bf16_kernel<2><<<gGemm, 256, GEMM_SMEM_BYTES>>>(
        inputs_kv, w_v, nullptr, vth, vtl, ROWS, EMB, EMB);

    dim3 gAttn(S_LEN / AQT, NH, BATCH);  // (64, 8, 2)
    attn_tc_kernel<<<gAttn, ATHREADS, ATTN_SMEM_BYTES>>>();

    gemm_bf16_kernel<0><<<gGemm, 256, GEMM_SMEM_BYTES>>>(
        ab, w_o, out, nullptr, nullptr, ROWS, EMB, EMB);
}

// round 17
// speedup vs baseline: 1.1412x; 1.1412x over previous
#include <cuda_runtime.h>
#include <math.h>
#include <stdint.h>

// Problem constants
constexpr int S_LEN = 4096;
constexpr int BATCH = 2;
constexpr int EMB   = 512;   // E and also H*D
constexpr int NH    = 8;
constexpr int DH    = 64;
constexpr int HALF  = 256;   // sliding window half-width
constexpr int ROWS  = BATCH * S_LEN;  // 8192
constexpr int KPR   = EMB / 2;        // 256 kpairs per row
constexpr int SHALF = S_LEN / 2;      // 2048 token-pairs

// Scratch (allocation-free rule: __device__ globals)
__device__ uint32_t g_qh[(size_t)ROWS * KPR];
__device__ uint32_t g_ql[(size_t)ROWS * KPR];
__device__ uint32_t g_kh[(size_t)ROWS * KPR];
__device__ uint32_t g_kl[(size_t)ROWS * KPR];
// V transposed planes: [b][dim][token-pair] u32 (bf16x2: t low, t+1 high)
__device__ uint32_t g_vth[(size_t)BATCH * EMB * SHALF];
__device__ uint32_t g_vtl[(size_t)BATCH * EMB * SHALF];
__device__ float    g_att[(size_t)ROWS * EMB];

// ---------------------------------------------------------------------------
// helpers
// ---------------------------------------------------------------------------
__device__ __forceinline__ void split2(float x0, float x1,
                                       uint32_t& hp, uint32_t& lp) {
    asm("cvt.rn.bf16x2.f32 %0, %1, %2;" : "=r"(hp) : "f"(x1), "f"(x0));
    float h0 = __uint_as_float(hp << 16);
    float h1 = __uint_as_float(hp & 0xffff0000u);
    float r0 = x0 - h0;
    float r1 = x1 - h1;
    asm("cvt.rn.bf16x2.f32 %0, %1, %2;" : "=r"(lp) : "f"(r1), "f"(r0));
}

__device__ __forceinline__ void mma_bf16(float d[4], const uint32_t a[4],
                                         const uint32_t b[2]) {
    asm volatile(
        "mma.sync.aligned.m16n8k16.row.col.f32.bf16.bf16.f32 "
        "{%0,%1,%2,%3}, {%4,%5,%6,%7}, {%8,%9}, {%0,%1,%2,%3};\n"
        : "+f"(d[0]), "+f"(d[1]), "+f"(d[2]), "+f"(d[3])
        : "r"(a[0]), "r"(a[1]), "r"(a[2]), "r"(a[3]), "r"(b[0]), "r"(b[1]));
}

__device__ __forceinline__ void ldsm_x4(uint32_t r[4], uint32_t addr) {
    asm volatile(
        "ldmatrix.sync.aligned.m8n8.x4.shared.b16 {%0,%1,%2,%3}, [%4];"
        : "=r"(r[0]), "=r"(r[1]), "=r"(r[2]), "=r"(r[3]) : "r"(addr));
}

__device__ __forceinline__ uint32_t smem_u32(const void* p) {
    return (uint32_t)__cvta_generic_to_shared(p);
}

// ---------------------------------------------------------------------------
// Split-bf16 tensor-core GEMM, single-buffered smem, 2 CTAs/SM (R13 form).
// C[M,N] = A[M,K] @ B[K,N]. MODE 0: fp32 C. MODE 1: bf16x2 hi/lo planes
// [row][kpair]. MODE 2: TRANSPOSED hi/lo planes [b][dim][token-pair] (for V).
// ---------------------------------------------------------------------------
constexpr int GBM = 128, GBN = 128, GBK = 32;
constexpr int KP  = GBK / 2;
constexpr int ASTR = 20;
constexpr int BSTR = 136;
constexpr int A_STAGE = GBM * ASTR;     // 2560
constexpr int B_STAGE = KP * BSTR;      // 2176
constexpr int GEMM_SMEM_BYTES = 2 * (A_STAGE + B_STAGE) * 4;  // 37888

template <int MODE>
__global__ __launch_bounds__(256, 2) void gemm_bf16_kernel(
    const float* __restrict__ A, const float* __restrict__ B,
    float* __restrict__ C, uint32_t* __restrict__ Ch, uint32_t* __restrict__ Cl,
    int M, int N, int K)
{
    extern __shared__ uint32_t sm[];
    uint32_t* sAh = sm;
    uint32_t* sAl = sAh + A_STAGE;
    uint32_t* sBh = sAl + A_STAGE;
    uint32_t* sBl = sBh + B_STAGE;

    const int tid  = threadIdx.x;
    const int lane = tid & 31;
    const int wid  = tid >> 5;
    const int m_base = (wid >> 2) * 64;
    const int n_base = (wid & 3) * 32;
    const int row0 = blockIdx.y * GBM;
    const int col0 = blockIdx.x * GBN;

    const int arow  = tid >> 2;
    const int acolg = (tid & 3) * 8;
    const int akp   = (tid & 3) * 4;
    const int brow = tid >> 5;
    const int bcol = (tid & 31) * 4;

    const float* pA0 = A + (size_t)(row0 + arow) * K + acolg;
    const float* pA1 = A + (size_t)(row0 + arow + 64) * K + acolg;
    const float* pB00 = B + (size_t)(2 * brow) * N + col0 + bcol;
    const float* pB01 = B + (size_t)(2 * brow + 1) * N + col0 + bcol;
    const float* pB10 = B + (size_t)(2 * (brow + 8)) * N + col0 + bcol;
    const float* pB11 = B + (size_t)(2 * (brow + 8) + 1) * N + col0 + bcol;

    const int NT = K / GBK;   // 16
    const int gr = lane >> 2;
    const int qc = lane & 3;

    float acc[4][4][4] = {};

    for (int kt = 0; kt < NT; kt++) {
        const int ko = kt * GBK;
        float4 fa00 = *(const float4*)(pA0 + ko);
        float4 fa01 = *(const float4*)(pA0 + ko + 4);
        float4 fa10 = *(const float4*)(pA1 + ko);
        float4 fa11 = *(const float4*)(pA1 + ko + 4);
        float4 fb00 = *(const float4*)(pB00 + (size_t)ko * N);
        float4 fb01 = *(const float4*)(pB01 + (size_t)ko * N);
        float4 fb10 = *(const float4*)(pB10 + (size_t)ko * N);
        float4 fb11 = *(const float4*)(pB11 + (size_t)ko * N);

        if (kt > 0) __syncthreads();

        {
            uint32_t h0, l0, h1, l1, h2, l2, h3, l3;
            split2(fa00.x, fa00.y, h0, l0);
            split2(fa00.z, fa00.w, h1, l1);
            split2(fa01.x, fa01.y, h2, l2);
            split2(fa01.z, fa01.w, h3, l3);
            *(uint4*)&sAh[arow * ASTR + akp] = make_uint4(h0, h1, h2, h3);
            *(uint4*)&sAl[arow * ASTR + akp] = make_uint4(l0, l1, l2, l3);
            split2(fa10.x, fa10.y, h0, l0);
            split2(fa10.z, fa10.w, h1, l1);
            split2(fa11.x, fa11.y, h2, l2);
            split2(fa11.z, fa11.w, h3, l3);
            *(uint4*)&sAh[(arow + 64) * ASTR + akp] = make_uint4(h0, h1, h2, h3);
            *(uint4*)&sAl[(arow + 64) * ASTR + akp] = make_uint4(l0, l1, l2, l3);
            split2(fb00.x, fb01.x, h0, l0);
            split2(fb00.y, fb01.y, h1, l1);
            split2(fb00.z, fb01.z, h2, l2);
            split2(fb00.w, fb01.w, h3, l3);
            *(uint4*)&sBh[brow * BSTR + bcol] = make_uint4(h0, h1, h2, h3);
            *(uint4*)&sBl[brow * BSTR + bcol] = make_uint4(l0, l1, l2, l3);
            split2(fb10.x, fb11.x, h0, l0);
            split2(fb10.y, fb11.y, h1, l1);
            split2(fb10.z, fb11.z, h2, l2);
            split2(fb10.w, fb11.w, h3, l3);
            *(uint4*)&sBh[(brow + 8) * BSTR + bcol] = make_uint4(h0, h1, h2, h3);
            *(uint4*)&sBl[(brow + 8) * BSTR + bcol] = make_uint4(l0, l1, l2, l3);
        }
        __syncthreads();

        #pragma unroll
        for (int ks = 0; ks < 2; ks++) {
            const int kp0 = ks * 8 + qc;
            uint32_t ah[4][4], al[4][4], bh[4][2], bl[4][2];
            #pragma unroll
            for (int mt = 0; mt < 4; mt++) {
                const int m = m_base + mt * 16 + gr;
                ah[mt][0] = sAh[m * ASTR + kp0];
                ah[mt][1] = sAh[(m + 8) * ASTR + kp0];
                ah[mt][2] = sAh[m * ASTR + kp0 + 4];
                ah[mt][3] = sAh[(m + 8) * ASTR + kp0 + 4];
                al[mt][0] = sAl[m * ASTR + kp0];
                al[mt][1] = sAl[(m + 8) * ASTR + kp0];
                al[mt][2] = sAl[m * ASTR + kp0 + 4];
                al[mt][3] = sAl[(m + 8) * ASTR + kp0 + 4];
            }
            #pragma unroll
            for (int nt = 0; nt < 4; nt++) {
                const int n = n_base + nt * 8 + gr;
                bh[nt][0] = sBh[kp0 * BSTR + n];
                bh[nt][1] = sBh[(kp0 + 4) * BSTR + n];
                bl[nt][0] = sBl[kp0 * BSTR + n];
                bl[nt][1] = sBl[(kp0 + 4) * BSTR + n];
            }
            #pragma unroll
            for (int mt = 0; mt < 4; mt++)
                #pragma unroll
                for (int nt = 0; nt < 4; nt++) {
                    mma_bf16(acc[mt][nt], ah[mt], bh[nt]);
                    mma_bf16(acc[mt][nt], ah[mt], bl[nt]);
                    mma_bf16(acc[mt][nt], al[mt], bh[nt]);
                }
        }
    }

    #pragma unroll
    for (int mt = 0; mt < 4; mt++) {
        #pragma unroll
        for (int nt = 0; nt < 4; nt++) {
            if constexpr (MODE == 2) {
                float e0 = acc[mt][nt][0], e1 = acc[mt][nt][1];
                float e2 = acc[mt][nt][2], e3 = acc[mt][nt][3];
                float p0 = __shfl_xor_sync(0xffffffffu, e0, 4);
                float p1 = __shfl_xor_sync(0xffffffffu, e1, 4);
                float p2 = __shfl_xor_sync(0xffffffffu, e2, 4);
                float p3 = __shfl_xor_sync(0xffffffffu, e3, 4);
                if ((gr & 1) == 0) {
                    int r = row0 + m_base + mt * 16 + gr;
                    int bb = r >> 12;
                    int t  = r & (S_LEN - 1);
                    int c  = col0 + n_base + nt * 8 + 2 * qc;
                    size_t b0 = ((size_t)bb * EMB + c) * SHALF + (t >> 1);
                    uint32_t hp, lp;
                    split2(e0, p0, hp, lp);
                    Ch[b0] = hp;               Cl[b0] = lp;
                    split2(e1, p1, hp, lp);
                    Ch[b0 + SHALF] = hp;       Cl[b0 + SHALF] = lp;
                    split2(e2, p2, hp, lp);
                    Ch[b0 + 4] = hp;           Cl[b0 + 4] = lp;
                    split2(e3, p3, hp, lp);
                    Ch[b0 + SHALF + 4] = hp;   Cl[b0 + SHALF + 4] = lp;
                }
            } else {
                int r = row0 + m_base + mt * 16 + gr;
                int c = col0 + n_base + nt * 8 + 2 * qc;
                if constexpr (MODE == 1) {
                    int kp = c >> 1;
                    uint32_t hp, lp;
                    split2(acc[mt][nt][0], acc[mt][nt][1], hp, lp);
                    Ch[(size_t)r * KPR + kp] = hp;
                    Cl[(size_t)r * KPR + kp] = lp;
                    split2(acc[mt][nt][2], acc[mt][nt][3], hp, lp);
                    Ch[(size_t)(r + 8) * KPR + kp] = hp;
                    Cl[(size_t)(r + 8) * KPR + kp] = lp;
                } else {
                    *(float2*)&C[(size_t)r * N + c] =
                        make_float2(acc[mt][nt][0], acc[mt][nt][1]);
                    *(float2*)&C[(size_t)(r + 8) * N + c] =
                        make_float2(acc[mt][nt][2], acc[mt][nt][3]);
                }
            }
        }
    }
}

// ---------------------------------------------------------------------------
// Attention: split-bf16, ldmatrix, pre-split inputs, fixed-max softmax,
// register-resident P, pre-transposed V with power-of-2 copy mapping,
// interior/boundary + full-window specialization.
// 256 threads, 6 chunks of 96 keys, 2 CTAs/SM.
// ---------------------------------------------------------------------------
constexpr int AQT = 64;
constexpr int AKT = 96;
constexpr int NCHUNK = 6;
constexpr int QSTR2 = 36;
constexpr int KSTR2 = 36;
constexpr int VSTR2 = 52;
constexpr int ATHREADS = 256;
constexpr float FIXM = 12.0f;

constexpr int OFF_QH = 0;
constexpr int OFF_QL = OFF_QH + AQT * QSTR2;
constexpr int OFF_KH = OFF_QL + AQT * QSTR2;
constexpr int OFF_KL = OFF_KH + AKT * KSTR2;
constexpr int OFF_VH = OFF_KL + AKT * KSTR2;
constexpr int OFF_VL = OFF_VH + 64 * VSTR2;
constexpr int OFF_RED = OFF_VL + 64 * VSTR2;
constexpr int OFF_ORED = OFF_RED + 128;
constexpr int ATTN_SMEM_WORDS = OFF_ORED + 64 * 66;
constexpr int ATTN_SMEM_BYTES = ATTN_SMEM_WORDS * 4;  // 90112

__global__ __launch_bounds__(ATHREADS, 2) void attn_tc_kernel()
{
    extern __shared__ uint32_t sm[];
    uint32_t* sQh = sm + OFF_QH;
    uint32_t* sQl = sm + OFF_QL;
    uint32_t* sKh = sm + OFF_KH;
    uint32_t* sKl = sm + OFF_KL;
    uint32_t* sVh = sm + OFF_VH;
    uint32_t* sVl = sm + OFF_VL;
    float* red  = (float*)(sm + OFF_RED);
    float* ored = (float*)(sm + OFF_ORED);

    const int tid  = threadIdx.x;
    const int lane = tid & 31;
    const int wid  = tid >> 5;
    const int gr = lane >> 2;
    const int qc = lane & 3;
    const int wm = wid >> 1;
    const int wn = wid & 1;
    const int m0 = wm * 16;

    const int t0 = blockIdx.x * AQT;
    const int h  = blockIdx.y;
    const int b  = blockIdx.z;
    const float slope = exp2f(-(float)(h + 1));

    const uint32_t* Qh_p = g_qh + ((size_t)(b * S_LEN + t0)) * KPR + h * 32;
    const uint32_t* Ql_p = g_ql + ((size_t)(b * S_LEN + t0)) * KPR + h * 32;
    const uint32_t* Kh_p = g_kh + ((size_t)b * S_LEN) * KPR + h * 32;
    const uint32_t* Kl_p = g_kl + ((size_t)b * S_LEN) * KPR + h * 32;
    const uint32_t* Vth_p = g_vth + ((size_t)b * EMB + h * DH) * SHALF;
    const uint32_t* Vtl_p = g_vtl + ((size_t)b * EMB + h * DH) * SHALF;
    float* Ob = g_att + (size_t)b * S_LEN * EMB + h * DH;

    const int lrow8  = (lane & 7);
    const int lmsel  = (lane >> 3) & 1;
    const int lhsel  = (lane >> 4) & 1;

    const uint32_t qh_base = smem_u32(sQh) +
        (((m0 + lrow8 + lmsel * 8) * QSTR2) + lhsel * 4) * 4;
    const uint32_t ql_base = qh_base + (OFF_QL - OFF_QH) * 4;
    const int nbase = wn * 48;
    const uint32_t kh_base = smem_u32(sKh) +
        (((nbase + lrow8 + lhsel * 8) * KSTR2) + lmsel * 4) * 4;
    const uint32_t kl_base = kh_base + (OFF_KL - OFF_KH) * 4;
    const uint32_t vh_base = smem_u32(sVh) +
        (((lrow8 + lhsel * 8) * VSTR2) + wn * 24 + lmsel * 4) * 4;
    const uint32_t vl_base = vh_base + (OFF_VL - OFF_VH) * 4;

    // V copy mapping: this thread owns dim dv, jj = qc + 4*it
    const int dv = wid * 8 + gr;

    for (int idx = tid; idx < 512; idx += ATHREADS) {
        int q = idx >> 3;
        int j = idx & 7;
        uint4 vh = *(const uint4*)&Qh_p[(size_t)q * KPR + j * 4];
        uint4 vl = *(const uint4*)&Ql_p[(size_t)q * KPR + j * 4];
        *(uint4*)&sQh[q * QSTR2 + j * 4] = vh;
        *(uint4*)&sQl[q * QSTR2 + j * 4] = vl;
    }

    float o[8][4] = {};
    float sum0 = 0.f, sum1 = 0.f;

    const int base = t0 - HALF;

    #pragma unroll 1
    for (int c = 0; c < NCHUNK; c++) {
        const int cs = base + c * AKT;
        if (cs + AKT <= 0 || cs >= S_LEN) continue;
        const bool inter = (cs >= 0) && (cs + AKT <= S_LEN);
        const int tp0 = cs >> 1;

        if (inter) {
            // ---- unguarded K copy ----
            #pragma unroll
            for (int it = 0; it < 3; it++) {
                int idx = tid + it * ATHREADS;
                int key = idx >> 3;
                int j = idx & 7;
                const size_t go = (size_t)(cs + key) * KPR + j * 4;
                *(uint4*)&sKh[key * KSTR2 + j * 4] = *(const uint4*)&Kh_p[go];
                *(uint4*)&sKl[key * KSTR2 + j * 4] = *(const uint4*)&Kl_p[go];
            }
            // ---- unguarded V copy (pre-transposed planes) ----
            #pragma unroll
            for (int it = 0; it < 3; it++) {
                int jj = qc + it * 4;
                const size_t go = (size_t)dv * SHALF + tp0 + jj * 4;
                *(uint4*)&sVh[dv * VSTR2 + jj * 4] = *(const uint4*)&Vth_p[go];
                *(uint4*)&sVl[dv * VSTR2 + jj * 4] = *(const uint4*)&Vtl_p[go];
            }
        } else {
            // ---- guarded K copy ----
            #pragma unroll
            for (int it = 0; it < 3; it++) {
                int idx = tid + it * ATHREADS;
                int key = idx >> 3;
                int j = idx & 7;
                int T = cs + key;
                uint4 vh = make_uint4(0, 0, 0, 0);
                uint4 vl = make_uint4(0, 0, 0, 0);
                if (T >= 0 && T < S_LEN) {
                    vh = *(const uint4*)&Kh_p[(size_t)T * KPR + j * 4];
                    vl = *(const uint4*)&Kl_p[(size_t)T * KPR + j * 4];
                }
                *(uint4*)&sKh[key * KSTR2 + j * 4] = vh;
                *(uint4*)&sKl[key * KSTR2 + j * 4] = vl;
            }
            // ---- guarded V copy (per-element) ----
            #pragma unroll
            for (int it = 0; it < 3; it++) {
                int jj = qc + it * 4;
                #pragma unroll
                for (int e = 0; e < 4; e++) {
                    int tp = tp0 + jj * 4 + e;
                    uint32_t vh = 0, vl = 0;
                    if (tp >= 0 && tp < SHALF) {
                        vh = Vth_p[(size_t)dv * SHALF + tp];
                        vl = Vtl_p[(size_t)dv * SHALF + tp];
                    }
                    sVh[dv * VSTR2 + jj * 4 + e] = vh;
                    sVl[dv * VSTR2 + jj * 4 + e] = vl;
                }
            }
        }
        __syncthreads();

        // ---- S = Q @ K^T ----
        float s[6][4];
        #pragma unroll
        for (int nt = 0; nt < 6; nt++)
            #pragma unroll
            for (int i = 0; i < 4; i++) s[nt][i] = 0.f;

        #pragma unroll
        for (int ks = 0; ks < 4; ks++) {
            uint32_t ah[4], al[4];
            ldsm_x4(ah, qh_base + ks * 32);
            ldsm_x4(al, ql_base + ks * 32);
            #pragma unroll
            for (int ntp = 0; ntp < 3; ntp++) {
                uint32_t bh[4], bl[4];
                ldsm_x4(bh, kh_base + ks * 32 + ntp * (16 * KSTR2 * 4));
                ldsm_x4(bl, kl_base + ks * 32 + ntp * (16 * KSTR2 * 4));
                mma_bf16(s[2 * ntp],     ah, bh);
                mma_bf16(s[2 * ntp],     ah, bl);
                mma_bf16(s[2 * ntp],     al, bh);
                mma_bf16(s[2 * ntp + 1], ah, bh + 2);
                mma_bf16(s[2 * ntp + 1], ah, bl + 2);
                mma_bf16(s[2 * ntp + 1], al, bh + 2);
            }
        }

        // ---- fixed-max softmax -> P packed into PV A-fragments ----
        const int trow0 = t0 + m0 + gr;
        const int trow1 = trow0 + 8;
        uint32_t pah[3][4], pal[3][4];
        const bool fullwin = inter && (c >= 1) && (c <= 4);
        if (fullwin) {
            #pragma unroll
            for (int nt = 0; nt < 6; nt++) {
                int T0 = cs + nbase + nt * 8 + 2 * qc;
                int T1 = T0 + 1;
                int a00 = abs(trow0 - T0), a01 = abs(trow0 - T1);
                int a10 = abs(trow1 - T0), a11 = abs(trow1 - T1);
                float p00 = __expf(fmaf(s[nt][0], 0.125f, fmaf(-slope, (float)a00, -FIXM)));
                float p01 = __expf(fmaf(s[nt][1], 0.125f, fmaf(-slope, (float)a01, -FIXM)));
                float p10 = __expf(fmaf(s[nt][2], 0.125f, fmaf(-slope, (float)a10, -FIXM)));
                float p11 = __expf(fmaf(s[nt][3], 0.125f, fmaf(-slope, (float)a11, -FIXM)));
                sum0 += p00 + p01;
                sum1 += p10 + p11;
                int ks = nt >> 1;
                int half = (nt & 1) * 2;
                uint32_t hp, lp;
                split2(p00, p01, hp, lp);
                pah[ks][half + 0] = hp;  pal[ks][half + 0] = lp;
                split2(p10, p11, hp, lp);
                pah[ks][half + 1] = hp;  pal[ks][half + 1] = lp;
            }
        } else {
            #pragma unroll
            for (int nt = 0; nt < 6; nt++) {
                int T0 = cs + nbase + nt * 8 + 2 * qc;
                int T1 = T0 + 1;
                bool in0 = (T0 >= 0) && (T0 < S_LEN);
                bool in1 = (T1 >= 0) && (T1 < S_LEN);
                int a00 = abs(trow0 - T0), a01 = abs(trow0 - T1);
                int a10 = abs(trow1 - T0), a11 = abs(trow1 - T1);
                float p00 = (in0 && a00 <= HALF)
                    ? __expf(fmaf(s[nt][0], 0.125f, fmaf(-slope, (float)a00, -FIXM))) : 0.f;
                float p01 = (in1 && a01 <= HALF)
                    ? __expf(fmaf(s[nt][1], 0.125f, fmaf(-slope, (float)a01, -FIXM))) : 0.f;
                float p10 = (in0 && a10 <= HALF)
                    ? __expf(fmaf(s[nt][2], 0.125f, fmaf(-slope, (float)a10, -FIXM))) : 0.f;
                float p11 = (in1 && a11 <= HALF)
                    ? __expf(fmaf(s[nt][3], 0.125f, fmaf(-slope, (float)a11, -FIXM))) : 0.f;
                sum0 += p00 + p01;
                sum1 += p10 + p11;
                int ks = nt >> 1;
                int half = (nt & 1) * 2;
                uint32_t hp, lp;
                split2(p00, p01, hp, lp);
                pah[ks][half + 0] = hp;  pal[ks][half + 0] = lp;
                split2(p10, p11, hp, lp);
                pah[ks][half + 1] = hp;  pal[ks][half + 1] = lp;
            }
        }

        // ---- O += P @ V ----
        #pragma unroll
        for (int ks = 0; ks < 3; ks++) {
            #pragma unroll
            for (int dt = 0; dt < 4; dt++) {
                uint32_t bh[4], bl[4];
                uint32_t off = (uint32_t)(dt * 16 * VSTR2 * 4 + ks * 32);
                ldsm_x4(bh, vh_base + off);
                ldsm_x4(bl, vl_base + off);
                mma_bf16(o[2 * dt],     pah[ks], bh);
                mma_bf16(o[2 * dt],     pah[ks], bl);
                mma_bf16(o[2 * dt],     pal[ks], bh);
                mma_bf16(o[2 * dt + 1], pah[ks], bh + 2);
                mma_bf16(o[2 * dt + 1], pah[ks], bl + 2);
                mma_bf16(o[2 * dt + 1], pal[ks], bh + 2);
            }
        }
        __syncthreads();
    }

    sum0 += __shfl_xor_sync(0xffffffffu, sum0, 1);
    sum0 += __shfl_xor_sync(0xffffffffu, sum0, 2);
    sum1 += __shfl_xor_sync(0xffffffffu, sum1, 1);
    sum1 += __shfl_xor_sync(0xffffffffu, sum1, 2);
    if (qc == 0) {
        red[(m0 + gr) * 2 + wn] = sum0;
        red[(m0 + gr + 8) * 2 + wn] = sum1;
    }
    if (wn == 1) {
        #pragma unroll
        for (int nt = 0; nt < 8; nt++) {
            int d = nt * 8 + 2 * qc;
            *(float2*)&ored[(m0 + gr) * 66 + d] = make_float2(o[nt][0], o[nt][1]);
            *(float2*)&ored[(m0 + gr + 8) * 66 + d] = make_float2(o[nt][2], o[nt][3]);
        }
    }
    __syncthreads();

    if (wn == 0) {
        const int trow0 = t0 + m0 + gr;
        const float inv0 = 1.0f / (red[(m0 + gr) * 2] + red[(m0 + gr) * 2 + 1]);
        const float inv1 = 1.0f / (red[(m0 + gr + 8) * 2] + red[(m0 + gr + 8) * 2 + 1]);
        #pragma unroll
        for (int nt = 0; nt < 8; nt++) {
            int d = nt * 8 + 2 * qc;
            float2 p0 = *(float2*)&ored[(m0 + gr) * 66 + d];
            float2 p1 = *(float2*)&ored[(m0 + gr + 8) * 66 + d];
            *(float2*)&Ob[(size_t)trow0 * EMB + d] =
                make_float2((o[nt][0] + p0.x) * inv0, (o[nt][1] + p0.y) * inv0);
            *(float2*)&Ob[(size_t)(trow0 + 8) * EMB + d] =
                make_float2((o[nt][2] + p1.x) * inv1, (o[nt][3] + p1.y) * inv1);
        }
    }
}

// ---------------------------------------------------------------------------
extern "C" void kernel_launch(void* const* d_in, const int* in_sizes, int n_in,
                              void* d_out, int out_size)
{
    (void)in_sizes; (void)n_in; (void)out_size;
    const float* inputs_q  = (const float*)d_in[0];
    const float* inputs_kv = (const float*)d_in[1];
    const float* w_q = (const float*)d_in[2];
    const float* w_k = (const float*)d_in[3];
    const float* w_v = (const float*)d_in[4];
    const float* w_o = (const float*)d_in[5];
    float* out = (float*)d_out;

    uint32_t *qh, *ql, *kh, *kl, *vth, *vtl;
    float* ab;
    cudaGetSymbolAddress((void**)&qh, g_qh);
    cudaGetSymbolAddress((void**)&ql, g_ql);
    cudaGetSymbolAddress((void**)&kh, g_kh);
    cudaGetSymbolAddress((void**)&kl, g_kl);
    cudaGetSymbolAddress((void**)&vth, g_vth);
    cudaGetSymbolAddress((void**)&vtl, g_vtl);
    cudaGetSymbolAddress((void**)&ab, g_att);

    cudaFuncSetAttribute(gemm_bf16_kernel<0>,
                         cudaFuncAttributeMaxDynamicSharedMemorySize,
                         GEMM_SMEM_BYTES);
    cudaFuncSetAttribute(gemm_bf16_kernel<1>,
                         cudaFuncAttributeMaxDynamicSharedMemorySize,
                         GEMM_SMEM_BYTES);
    cudaFuncSetAttribute(gemm_bf16_kernel<2>,
                         cudaFuncAttributeMaxDynamicSharedMemorySize,
                         GEMM_SMEM_BYTES);
    cudaFuncSetAttribute(attn_tc_kernel,
                         cudaFuncAttributeMaxDynamicSharedMemorySize,
                         ATTN_SMEM_BYTES);

    dim3 gGemm(EMB / GBN, ROWS / GBM);   // (4, 64)
    gemm_bf16_kernel<1><<<gGemm, 256, GEMM_SMEM_BYTES>>>(
        inputs_q,  w_q, nullptr, qh, ql, ROWS, EMB, EMB);
    gemm_bf16_kernel<1><<<gGemm, 256, GEMM_SMEM_BYTES>>>(
        inputs_kv, w_k, nullptr, kh, kl, ROWS, EMB, EMB);
    gemm_bf16_kernel<2><<<gGemm, 256, GEMM_SMEM_BYTES>>>(
        inputs_kv, w_v, nullptr, vth, vtl, ROWS, EMB, EMB);

    dim3 gAttn(S_LEN / AQT, NH, BATCH);  // (64, 8, 2)
    attn_tc_kernel<<<gAttn, ATHREADS, ATTN_SMEM_BYTES>>>();

    gemm_bf16_kernel<0><<<gGemm, 256, GEMM_SMEM_BYTES>>>(
        ab, w_o, out, nullptr, nullptr, ROWS, EMB, EMB);
}